// round 8
// baseline (speedup 1.0000x reference)
#include <cuda_runtime.h>

#define NT    8
#define NRES  500
#define NBINS 34
#define KCB   150.0f

__device__ __forceinline__ float ex2a(float x)  { float r; asm("ex2.approx.ftz.f32 %0, %1;"  : "=f"(r) : "f"(x)); return r; }
__device__ __forceinline__ float frcpa(float x) { float r; asm("rcp.approx.ftz.f32 %0, %1;"  : "=f"(r) : "f"(x)); return r; }
__device__ __forceinline__ float fsqrta(float x){ float r; asm("sqrt.approx.ftz.f32 %0, %1;" : "=f"(r) : "f"(x)); return r; }

// Thread map: t = tid & 7 (trajectory), iLane = tid >> 3 (i stride 32).
// One distance per thread -> tiny register state -> 4 CTAs/SM -> 592 slots:
// the whole grid (500) runs in ONE wave.
__global__ __launch_bounds__(256, 4) void force_folder_kernel(
    const float* __restrict__ coords,   // [NT, NRES, 3]
    const float* __restrict__ gw,       // [NRES, NRES, NBINS]
    const float* __restrict__ centres,  // [NBINS]
    const float* __restrict__ sigmas,   // [NBINS]
    float* __restrict__ out)            // [NT, NRES, 3]
{
    const int j     = blockIdx.x;
    const int tid   = threadIdx.x;
    const int t     = tid & 7;
    const int iLane = tid >> 3;

    // Per-bin constants, folded:
    //   e  = 2^(-(d*isp + mcsp)^2)          isp = sqrt(0.5*log2(e))/sigma
    //   p  = fma(d, a3, b3) = (c-d)/sigma^3  a3 = -1/s^3, b3 = c/s^3
    //   force += (p*w) * e
    __shared__ float4 s_bin[NBINS];
    __shared__ float  s_cbj[NT * 3];
    __shared__ float  s_red[8][NT * 3];
    __shared__ float  s_geom[3];   // c0, 1/dc, R (window half-width)

    if (tid < NBINS) {
        float s  = sigmas[tid];
        float c  = centres[tid];
        float is = 1.0f / s;
        const float s2 = 0.84932181f;   // sqrt(0.5 * log2(e))
        float is3 = is * is * is;
        s_bin[tid] = make_float4(is * s2, -c * is * s2, -is3, c * is3);
    }
    if (tid < NT * 3) {
        int tt = tid / 3, cc = tid - tt * 3;
        s_cbj[tid] = coords[(tt * NRES + j) * 3 + cc];
    }
    if (tid == 0) {
        float smax = 0.0f;
        #pragma unroll
        for (int b = 0; b < NBINS; b++) smax = fmaxf(smax, sigmas[b]);
        float c0 = centres[0];
        float dc = centres[1] - centres[0];
        s_geom[0] = c0;
        s_geom[1] = 1.0f / dc;
        s_geom[2] = 5.0f * smax;   // 5-sigma window: exp(-12.5)=3.7e-6 tail
    }
    __syncthreads();

    const float c0 = s_geom[0], inv_dc = s_geom[1], R = s_geom[2];
    const float cjx = s_cbj[t * 3 + 0];
    const float cjy = s_cbj[t * 3 + 1];
    const float cjz = s_cbj[t * 3 + 2];
    const float* __restrict__ cbase = coords + (long)t * NRES * 3;

    float ax = 0.f, ay = 0.f, az = 0.f;

    for (int i = iLane; i < NRES; i += 32) {
        float cix = cbase[i * 3 + 0];
        float ciy = cbase[i * 3 + 1];
        float ciz = cbase[i * 3 + 2];
        float dx = cjx - cix, dy = cjy - ciy, dz = cjz - ciz;
        float ss = fmaf(dx, dx, fmaf(dy, dy, dz * dz));
        float d  = fminf(fmaxf(fsqrta(ss), 0.1f), 40.0f);

        // active bin window: |d - c_b| <= R  (uniform centre grid)
        int blo = (int)ceilf ((d - R - c0) * inv_dc);
        int bhi = (int)floorf((d + R - c0) * inv_dc) + 1;
        blo = max(blo, 0);
        bhi = min(bhi, NBINS);

        float force = 0.0f;
        const float* __restrict__ wrow = gw + ((long)i * NRES + j) * NBINS;
        #pragma unroll 2
        for (int b = blo; b < bhi; b++) {
            float4 bc = s_bin[b];
            float  w  = __ldg(wrow + b);
            float  q  = fmaf(d, bc.x, bc.y);     // (d-c)*s2/sigma
            float  e  = ex2a(-q * q);            // exp(-0.5((d-c)/sigma)^2)
            float  p  = fmaf(d, bc.z, bc.w);     // (c-d)/sigma^3
            force = fmaf(p * w, e, force);
        }

        float coef = -KCB * force * frcpa(d);
        ax = fmaf(coef, dx, ax);
        ay = fmaf(coef, dy, ay);
        az = fmaf(coef, dz, az);
    }

    // Same-t lanes within a warp sit at lane offsets {0,8,16,24}.
    ax += __shfl_down_sync(0xffffffffu, ax, 16);
    ax += __shfl_down_sync(0xffffffffu, ax, 8);
    ay += __shfl_down_sync(0xffffffffu, ay, 16);
    ay += __shfl_down_sync(0xffffffffu, ay, 8);
    az += __shfl_down_sync(0xffffffffu, az, 16);
    az += __shfl_down_sync(0xffffffffu, az, 8);

    const int lane = tid & 31, warp = tid >> 5;
    if (lane < 8) {   // lane == t here
        s_red[warp][lane * 3 + 0] = ax;
        s_red[warp][lane * 3 + 1] = ay;
        s_red[warp][lane * 3 + 2] = az;
    }
    __syncthreads();
    if (tid < NT * 3) {
        float s = 0.f;
        #pragma unroll
        for (int w = 0; w < 8; w++) s += s_red[w][tid];
        int tt = tid / 3, cc = tid - tt * 3;
        out[(tt * NRES + j) * 3 + cc] = s;
    }
}

extern "C" void kernel_launch(void* const* d_in, const int* in_sizes, int n_in,
                              void* d_out, int out_size) {
    const float* coords  = (const float*)d_in[0];
    const float* gw      = (const float*)d_in[1];
    const float* centres = (const float*)d_in[2];
    const float* sigmas  = (const float*)d_in[3];
    force_folder_kernel<<<NRES, 256>>>(coords, gw, centres, sigmas, (float*)d_out);
}

// round 9
// speedup vs baseline: 1.2772x; 1.2772x over previous
#include <cuda_runtime.h>

#define NT    8
#define NRES  500
#define NBINS 34
#define KCB   150.0f
#define CHUNK 256
#define WPAD  35   // 34 bins padded to 35: stride-35 LDS is bank-conflict-free

__device__ __forceinline__ float ex2a(float x)  { float r; asm("ex2.approx.ftz.f32 %0, %1;"  : "=f"(r) : "f"(x)); return r; }
__device__ __forceinline__ float frcpa(float x) { float r; asm("rcp.approx.ftz.f32 %0, %1;"  : "=f"(r) : "f"(x)); return r; }
__device__ __forceinline__ float fsqrta(float x){ float r; asm("sqrt.approx.ftz.f32 %0, %1;" : "=f"(r) : "f"(x)); return r; }

// Math: q = (d-c)*s2/sigma  with s2 = sqrt(0.5*log2(e))
//       exp(-0.5((d-c)/sigma)^2) = 2^(-q*q) = ex2a(-q*q)
//       -(d-c)/sigma^2 * w/sigma = q * (w * kb),  kb = -1/(s2*sigma^2)
// Per (t,b) eval: FMA(q) + FMUL(-q*q) + MUFU + FMUL(q*wq) + FMA(acc) = 4 fma-pipe + 1 mufu.
__global__ __launch_bounds__(256) void force_folder_kernel(
    const float* __restrict__ coords,   // [NT, NRES, 3]
    const float* __restrict__ gw,       // [NRES, NRES, NBINS]
    const float* __restrict__ centres,  // [NBINS]
    const float* __restrict__ sigmas,   // [NBINS]
    float* __restrict__ out)            // [NT, NRES, 3]
{
    const int j   = blockIdx.x;
    const int tid = threadIdx.x;

    __shared__ float  s_w[CHUNK * WPAD];       // staged weight rows (35840 B)
    __shared__ float4 s_bin[NBINS];            // (isp, mcsp, kb, unused)
    __shared__ float  s_cbj[NT * 3];
    __shared__ float  s_part[NT * 3][8];

    if (tid < NBINS) {
        float s  = sigmas[tid];
        float c  = centres[tid];
        float is = 1.0f / s;
        const float s2 = 0.84932181f;          // sqrt(0.5 * log2(e))
        float isp = is * s2;
        s_bin[tid] = make_float4(isp, -c * isp, -is * is / s2, 0.0f);
    }
    if (tid < NT * 3) {
        int t = tid / 3, cc = tid - t * 3;
        s_cbj[tid] = coords[(t * NRES + j) * 3 + cc];
    }

    float acc[NT][3];
    #pragma unroll
    for (int t = 0; t < NT; t++) { acc[t][0] = 0.f; acc[t][1] = 0.f; acc[t][2] = 0.f; }

    for (int c0 = 0; c0 < NRES; c0 += CHUNK) {
        const int C = min(CHUNK, NRES - c0);

        __syncthreads();   // protect s_w reuse across chunks (and cover init stores)

        // ---- Phase 1: coalesced stage of C weight rows into smem ----
        // Consecutive threads read consecutive floats of a row -> ~1 line/warp-instr
        // (vs 32 lines/instr when lanes read their own rows directly).
        for (int idx = tid; idx < C * NBINS; idx += 256) {
            int r = idx / NBINS;
            int b = idx - r * NBINS;
            s_w[r * WPAD + b] = gw[((long)(c0 + r) * NRES + j) * NBINS + b];
        }
        __syncthreads();

        // ---- Phase 2: compute; thread owns row i = c0 + tid ----
        if (tid < C) {
            const int i = c0 + tid;
            const float* __restrict__ wrow = s_w + tid * WPAD;

            float d[NT], force[NT];
            #pragma unroll
            for (int t = 0; t < NT; t++) {
                const float* ci = coords + (t * NRES + i) * 3;
                float dx = s_cbj[t * 3 + 0] - ci[0];
                float dy = s_cbj[t * 3 + 1] - ci[1];
                float dz = s_cbj[t * 3 + 2] - ci[2];
                float ss = fmaf(dx, dx, fmaf(dy, dy, dz * dz));
                d[t] = fminf(fmaxf(fsqrta(ss), 0.1f), 40.0f);
                force[t] = 0.0f;
            }

            #pragma unroll 2
            for (int b = 0; b < NBINS; b++) {
                float4 bc = s_bin[b];
                float  wq = wrow[b] * bc.z;          // w * kb, amortized over 8 t
                #pragma unroll
                for (int t = 0; t < NT; t++) {
                    float q = fmaf(d[t], bc.x, bc.y);
                    float e = ex2a(-q * q);
                    force[t] = fmaf(q * wq, e, force[t]);
                }
            }

            #pragma unroll
            for (int t = 0; t < NT; t++) {
                const float* ci = coords + (t * NRES + i) * 3;
                float coef = -KCB * force[t] * frcpa(d[t]);
                acc[t][0] = fmaf(coef, s_cbj[t * 3 + 0] - ci[0], acc[t][0]);
                acc[t][1] = fmaf(coef, s_cbj[t * 3 + 1] - ci[1], acc[t][1]);
                acc[t][2] = fmaf(coef, s_cbj[t * 3 + 2] - ci[2], acc[t][2]);
            }
        }
    }

    // ---- Block reduction over i lanes ----
    const int lane = tid & 31, warp = tid >> 5;
    #pragma unroll
    for (int t = 0; t < NT; t++) {
        #pragma unroll
        for (int c = 0; c < 3; c++) {
            float v = acc[t][c];
            v += __shfl_down_sync(0xffffffffu, v, 16);
            v += __shfl_down_sync(0xffffffffu, v, 8);
            v += __shfl_down_sync(0xffffffffu, v, 4);
            v += __shfl_down_sync(0xffffffffu, v, 2);
            v += __shfl_down_sync(0xffffffffu, v, 1);
            if (lane == 0) s_part[t * 3 + c][warp] = v;
        }
    }
    __syncthreads();
    if (tid < NT * 3) {
        float s = 0.f;
        #pragma unroll
        for (int w = 0; w < 8; w++) s += s_part[tid][w];
        int t = tid / 3, cc = tid - t * 3;
        out[(t * NRES + j) * 3 + cc] = s;
    }
}

extern "C" void kernel_launch(void* const* d_in, const int* in_sizes, int n_in,
                              void* d_out, int out_size) {
    const float* coords  = (const float*)d_in[0];
    const float* gw      = (const float*)d_in[1];
    const float* centres = (const float*)d_in[2];
    const float* sigmas  = (const float*)d_in[3];
    force_folder_kernel<<<NRES, 256>>>(coords, gw, centres, sigmas, (float*)d_out);
}

// round 10
// speedup vs baseline: 1.5188x; 1.1891x over previous
#include <cuda_runtime.h>

#define NT    8
#define NRES  500
#define NBINS 34
#define KCB   150.0f

__device__ __forceinline__ float ex2a(float x)  { float r; asm("ex2.approx.ftz.f32 %0, %1;"  : "=f"(r) : "f"(x)); return r; }
__device__ __forceinline__ float frcpa(float x) { float r; asm("rcp.approx.ftz.f32 %0, %1;"  : "=f"(r) : "f"(x)); return r; }
__device__ __forceinline__ float fsqrta(float x){ float r; asm("sqrt.approx.ftz.f32 %0, %1;" : "=f"(r) : "f"(x)); return r; }

// Math: q = (d - c) * s2/sigma,  s2 = sqrt(0.5*log2(e))
//       exp(-0.5((d-c)/sigma)^2) = 2^(-q*q)
//       contribution = -(d-c)/sigma^2 * w/sigma * e = q * (w*kb) * e, kb = -1/(s2*sigma^2)
// Per (t,b) eval: FMA(q) + FMUL(-q*q) + MUFU(ex2) + FMUL(q*wq...) folded:
//   force = fma(q*wq, e, force) -> FMUL + FMA. Total 4 fma-pipe + 1 mufu.
__global__ __launch_bounds__(256, 3) void force_folder_kernel(
    const float* __restrict__ coords,   // [NT, NRES, 3]
    const float* __restrict__ gw,       // [NRES, NRES, NBINS]
    const float* __restrict__ centres,  // [NBINS]
    const float* __restrict__ sigmas,   // [NBINS]
    float* __restrict__ out)            // [NT, NRES, 3]
{
    const int j   = blockIdx.x;
    const int tid = threadIdx.x;

    __shared__ float2 s_qc[NBINS];      // (isp, mcsp)
    __shared__ float  s_kb[NBINS];      // kb = -1/(s2*sigma^2)
    __shared__ float  s_cbj[NT * 3];
    __shared__ float  s_part[NT * 3][8];

    if (tid < NBINS) {
        float s  = sigmas[tid];
        float c  = centres[tid];
        float is = 1.0f / s;
        const float s2 = 0.84932181f;   // sqrt(0.5 * log2(e))
        float isp = is * s2;
        s_qc[tid] = make_float2(isp, -c * isp);
        s_kb[tid] = -is * is / s2;
    }
    if (tid < NT * 3) {
        int t = tid / 3, cc = tid - t * 3;
        s_cbj[tid] = coords[(t * NRES + j) * 3 + cc];
    }
    __syncthreads();

    float acc[NT][3];
    #pragma unroll
    for (int t = 0; t < NT; t++) { acc[t][0] = 0.f; acc[t][1] = 0.f; acc[t][2] = 0.f; }

    for (int i = tid; i < NRES; i += 256) {
        const float* __restrict__ wrow = gw + ((long)i * NRES + j) * NBINS;
        float d[NT], force[NT];
        #pragma unroll
        for (int t = 0; t < NT; t++) {
            const float* ci = coords + (t * NRES + i) * 3;
            float dx = s_cbj[t * 3 + 0] - ci[0];
            float dy = s_cbj[t * 3 + 1] - ci[1];
            float dz = s_cbj[t * 3 + 2] - ci[2];
            float ss = fmaf(dx, dx, fmaf(dy, dy, dz * dz));
            d[t] = fminf(fmaxf(fsqrta(ss), 0.1f), 40.0f);
            force[t] = 0.0f;
        }

        #pragma unroll 2
        for (int b = 0; b < NBINS; b++) {
            float2 qc = s_qc[b];
            float  wq = wrow[b] * s_kb[b];        // amortized over 8 trajs
            #pragma unroll
            for (int t = 0; t < NT; t++) {
                float q = fmaf(d[t], qc.x, qc.y); // (d-c)*s2/sigma
                float e = ex2a(-q * q);           // exp(-0.5((d-c)/sigma)^2)
                force[t] = fmaf(q * wq, e, force[t]);
            }
        }

        #pragma unroll
        for (int t = 0; t < NT; t++) {
            const float* ci = coords + (t * NRES + i) * 3;
            float coef = -KCB * force[t] * frcpa(d[t]);
            acc[t][0] = fmaf(coef, s_cbj[t * 3 + 0] - ci[0], acc[t][0]);
            acc[t][1] = fmaf(coef, s_cbj[t * 3 + 1] - ci[1], acc[t][1]);
            acc[t][2] = fmaf(coef, s_cbj[t * 3 + 2] - ci[2], acc[t][2]);
        }
    }

    // Block reduction over i: shfl within warp, then smem across 8 warps.
    const int lane = tid & 31, warp = tid >> 5;
    #pragma unroll
    for (int t = 0; t < NT; t++) {
        #pragma unroll
        for (int c = 0; c < 3; c++) {
            float v = acc[t][c];
            v += __shfl_down_sync(0xffffffffu, v, 16);
            v += __shfl_down_sync(0xffffffffu, v, 8);
            v += __shfl_down_sync(0xffffffffu, v, 4);
            v += __shfl_down_sync(0xffffffffu, v, 2);
            v += __shfl_down_sync(0xffffffffu, v, 1);
            if (lane == 0) s_part[t * 3 + c][warp] = v;
        }
    }
    __syncthreads();
    if (tid < NT * 3) {
        float s = 0.f;
        #pragma unroll
        for (int w = 0; w < 8; w++) s += s_part[tid][w];
        int t = tid / 3, cc = tid - t * 3;
        out[(t * NRES + j) * 3 + cc] = s;
    }
}

extern "C" void kernel_launch(void* const* d_in, const int* in_sizes, int n_in,
                              void* d_out, int out_size) {
    const float* coords  = (const float*)d_in[0];
    const float* gw      = (const float*)d_in[1];
    const float* centres = (const float*)d_in[2];
    const float* sigmas  = (const float*)d_in[3];
    force_folder_kernel<<<NRES, 256>>>(coords, gw, centres, sigmas, (float*)d_out);
}

// round 11
// speedup vs baseline: 2.1148x; 1.3924x over previous
#include <cuda_runtime.h>

#define NT    8
#define NRES  500
#define NBINS 34
#define KCB   150.0f
#define WPAD  35   // stride-35 LDS: gcd(35,32)=1 -> conflict-free row reads

__device__ __forceinline__ float ex2a(float x)  { float r; asm("ex2.approx.ftz.f32 %0, %1;"  : "=f"(r) : "f"(x)); return r; }
__device__ __forceinline__ float frcpa(float x) { float r; asm("rcp.approx.ftz.f32 %0, %1;"  : "=f"(r) : "f"(x)); return r; }
__device__ __forceinline__ float fsqrta(float x){ float r; asm("sqrt.approx.ftz.f32 %0, %1;" : "=f"(r) : "f"(x)); return r; }

// Math (validated R9/R10, rel_err ~2e-7):
//   q = (d - c) * s2/sigma,  s2 = sqrt(0.5*log2(e))
//   exp(-0.5((d-c)/sigma)^2) = 2^(-q*q)
//   contribution = q * (w*kb) * e,  kb = -1/(s2*sigma^2)
// Per (t,b) eval: FMA + FMUL + MUFU + FMUL + FMA = 4 fma-pipe + 1 mufu.
__global__ __launch_bounds__(256) void force_folder_kernel(
    const float* __restrict__ coords,   // [NT, NRES, 3]
    const float* __restrict__ gw,       // [NRES, NRES, NBINS]
    const float* __restrict__ centres,  // [NBINS]
    const float* __restrict__ sigmas,   // [NBINS]
    float* __restrict__ out)            // [NT, NRES, 3]
{
    const int j    = blockIdx.x;
    const int tid  = threadIdx.x;
    const int warp = tid >> 5;
    const int lane = tid & 31;

    __shared__ float  s_w[8][32 * WPAD];   // per-warp slice: 32 weight rows
    __shared__ float2 s_qc[NBINS];         // (isp, mcsp)
    __shared__ float  s_kb[NBINS];
    __shared__ float  s_cbj[NT * 3];
    __shared__ float  s_part[NT * 3][8];

    if (tid < NBINS) {
        float s  = sigmas[tid];
        float c  = centres[tid];
        float is = 1.0f / s;
        const float s2 = 0.84932181f;      // sqrt(0.5 * log2(e))
        float isp = is * s2;
        s_qc[tid] = make_float2(isp, -c * isp);
        s_kb[tid] = -is * is / s2;
    }
    if (tid < NT * 3) {
        int t = tid / 3, cc = tid - t * 3;
        s_cbj[tid] = coords[(t * NRES + j) * 3 + cc];
    }
    __syncthreads();

    float acc[NT][3];
    #pragma unroll
    for (int t = 0; t < NT; t++) { acc[t][0] = 0.f; acc[t][1] = 0.f; acc[t][2] = 0.f; }

    float* __restrict__ sw = &s_w[warp][0];

    #pragma unroll
    for (int iter = 0; iter < 2; iter++) {
        const int ibase = iter * 256 + warp * 32;   // first row this warp owns

        __syncwarp();   // previous iteration's reads done before overwrite

        // ---- Warp-local staging: 32 rows x 17 float2, lanes spread ACROSS
        // rows (k = lane + 32*it, row = k/17) -> ~2 rows (~4 lines) per
        // warp-instr instead of 32 lines. No block barrier: each warp
        // produces and consumes its own slice.
        #pragma unroll
        for (int it = 0; it < 17; it++) {
            int k = it * 32 + lane;                 // 0..543 over 544 float2
            int r = k / 17;
            int c = k - r * 17;
            int rg = min(ibase + r, NRES - 1);      // clamp tail rows
            const float2 w2 = *(const float2*)(gw + ((long)rg * NRES + j) * NBINS + 2 * c);
            sw[r * WPAD + 2 * c]     = w2.x;
            sw[r * WPAD + 2 * c + 1] = w2.y;
        }
        __syncwarp();

        const int i = ibase + lane;
        if (i < NRES) {
            const float* __restrict__ wrow = sw + lane * WPAD;

            float d[NT], force[NT];
            #pragma unroll
            for (int t = 0; t < NT; t++) {
                const float* ci = coords + (t * NRES + i) * 3;
                float dx = s_cbj[t * 3 + 0] - ci[0];
                float dy = s_cbj[t * 3 + 1] - ci[1];
                float dz = s_cbj[t * 3 + 2] - ci[2];
                float ss = fmaf(dx, dx, fmaf(dy, dy, dz * dz));
                d[t] = fminf(fmaxf(fsqrta(ss), 0.1f), 40.0f);
                force[t] = 0.0f;
            }

            #pragma unroll 2
            for (int b = 0; b < NBINS; b++) {
                float2 qc = s_qc[b];
                float  wq = wrow[b] * s_kb[b];      // amortized over 8 trajs
                #pragma unroll
                for (int t = 0; t < NT; t++) {
                    float q = fmaf(d[t], qc.x, qc.y);
                    float e = ex2a(-q * q);
                    force[t] = fmaf(q * wq, e, force[t]);
                }
            }

            #pragma unroll
            for (int t = 0; t < NT; t++) {
                const float* ci = coords + (t * NRES + i) * 3;
                float coef = -KCB * force[t] * frcpa(d[t]);
                acc[t][0] = fmaf(coef, s_cbj[t * 3 + 0] - ci[0], acc[t][0]);
                acc[t][1] = fmaf(coef, s_cbj[t * 3 + 1] - ci[1], acc[t][1]);
                acc[t][2] = fmaf(coef, s_cbj[t * 3 + 2] - ci[2], acc[t][2]);
            }
        }
    }

    // ---- Block reduction over i lanes ----
    #pragma unroll
    for (int t = 0; t < NT; t++) {
        #pragma unroll
        for (int c = 0; c < 3; c++) {
            float v = acc[t][c];
            v += __shfl_down_sync(0xffffffffu, v, 16);
            v += __shfl_down_sync(0xffffffffu, v, 8);
            v += __shfl_down_sync(0xffffffffu, v, 4);
            v += __shfl_down_sync(0xffffffffu, v, 2);
            v += __shfl_down_sync(0xffffffffu, v, 1);
            if (lane == 0) s_part[t * 3 + c][warp] = v;
        }
    }
    __syncthreads();
    if (tid < NT * 3) {
        float s = 0.f;
        #pragma unroll
        for (int w = 0; w < 8; w++) s += s_part[tid][w];
        int t = tid / 3, cc = tid - t * 3;
        out[(t * NRES + j) * 3 + cc] = s;
    }
}

extern "C" void kernel_launch(void* const* d_in, const int* in_sizes, int n_in,
                              void* d_out, int out_size) {
    const float* coords  = (const float*)d_in[0];
    const float* gw      = (const float*)d_in[1];
    const float* centres = (const float*)d_in[2];
    const float* sigmas  = (const float*)d_in[3];
    force_folder_kernel<<<NRES, 256>>>(coords, gw, centres, sigmas, (float*)d_out);
}

// round 12
// speedup vs baseline: 2.2459x; 1.0620x over previous
#include <cuda_runtime.h>

#define NT    8
#define NRES  500
#define NBINS 34
#define KCB   150.0f
#define WPAD  35      // stride-35 LDS rows: gcd(35,32)=1 -> conflict-free
#define ROWS  128     // i-rows per block
#define NCHUNK 4      // ceil(500/128)

__device__ __forceinline__ float ex2a(float x)  { float r; asm("ex2.approx.ftz.f32 %0, %1;"  : "=f"(r) : "f"(x)); return r; }
__device__ __forceinline__ float frcpa(float x) { float r; asm("rcp.approx.ftz.f32 %0, %1;"  : "=f"(r) : "f"(x)); return r; }
__device__ __forceinline__ float fsqrta(float x){ float r; asm("sqrt.approx.ftz.f32 %0, %1;" : "=f"(r) : "f"(x)); return r; }

__global__ void zero_kernel(float* __restrict__ out, int n) {
    int i = blockIdx.x * blockDim.x + threadIdx.x;
    if (i < n) out[i] = 0.0f;
}

// Thread layout: tg = tid>>7 selects trajectories {tg*4..tg*4+3},
//                il = tid&127 selects i-row within this block's 128-row chunk.
// Math (validated, rel_err ~2e-7):
//   q = (d - c) * s2/sigma, s2 = sqrt(0.5*log2(e)); exp term = 2^(-q*q)
//   contribution = q * (w*kb) * e,  kb = -1/(s2*sigma^2)
__global__ __launch_bounds__(256, 3) void force_folder_kernel(
    const float* __restrict__ coords,   // [NT, NRES, 3]
    const float* __restrict__ gw,       // [NRES, NRES, NBINS]
    const float* __restrict__ centres,  // [NBINS]
    const float* __restrict__ sigmas,   // [NBINS]
    float* __restrict__ out)            // [NT, NRES, 3], pre-zeroed
{
    const int chunk = blockIdx.x;
    const int j     = blockIdx.y;
    const int tid   = threadIdx.x;
    const int warp  = tid >> 5;
    const int lane  = tid & 31;
    const int tg    = tid >> 7;     // trajectory group 0/1
    const int il    = tid & 127;    // i-lane within chunk

    __shared__ float  s_w[ROWS * WPAD];   // 128 weight rows, shared by both tg
    __shared__ float2 s_qc[NBINS];        // (isp, mcsp)
    __shared__ float  s_kb[NBINS];
    __shared__ float  s_cbj[NT * 3];
    __shared__ float  s_part[8][12];

    if (tid < NBINS) {
        float s  = sigmas[tid];
        float c  = centres[tid];
        float is = 1.0f / s;
        const float s2 = 0.84932181f;     // sqrt(0.5 * log2(e))
        float isp = is * s2;
        s_qc[tid] = make_float2(isp, -c * isp);
        s_kb[tid] = -is * is / s2;
    }
    if (tid < NT * 3) {
        int t = tid / 3, cc = tid - t * 3;
        s_cbj[tid] = coords[(t * NRES + j) * 3 + cc];
    }

    // ---- Cooperative coalesced staging: warp (g = warp&3, h = warp>>2)
    // stages rows [g*32 + h*16, +16), 17 float2 per row, lanes spread across
    // rows -> ~4 lines per warp-instr instead of 32.
    {
        const int g = warp & 3, h = warp >> 2;
        const int rbase = g * 32 + h * 16;
        #pragma unroll
        for (int it = 0; it < 9; it++) {
            int k = it * 32 + lane;               // 0..287; 272 valid
            if (k < 16 * 17) {
                int r = k / 17;
                int c = k - r * 17;
                int rl = rbase + r;
                int rg2 = min(chunk * ROWS + rl, NRES - 1);
                const float2 w2 = *(const float2*)(gw + ((long)rg2 * NRES + j) * NBINS + 2 * c);
                s_w[rl * WPAD + 2 * c]     = w2.x;
                s_w[rl * WPAD + 2 * c + 1] = w2.y;
            }
        }
    }
    __syncthreads();

    float acc[4][3];
    #pragma unroll
    for (int tl = 0; tl < 4; tl++) { acc[tl][0] = 0.f; acc[tl][1] = 0.f; acc[tl][2] = 0.f; }

    const int i = chunk * ROWS + il;
    if (i < NRES) {
        const float* __restrict__ wrow = s_w + il * WPAD;

        float d[4], force[4];
        #pragma unroll
        for (int tl = 0; tl < 4; tl++) {
            int t = tg * 4 + tl;
            const float* ci = coords + (t * NRES + i) * 3;
            float dx = s_cbj[t * 3 + 0] - ci[0];
            float dy = s_cbj[t * 3 + 1] - ci[1];
            float dz = s_cbj[t * 3 + 2] - ci[2];
            float ss = fmaf(dx, dx, fmaf(dy, dy, dz * dz));
            d[tl] = fminf(fmaxf(fsqrta(ss), 0.1f), 40.0f);
            force[tl] = 0.0f;
        }

        #pragma unroll 2
        for (int b = 0; b < NBINS; b++) {
            float2 qc = s_qc[b];
            float  wq = wrow[b] * s_kb[b];       // amortized over 4 trajs
            #pragma unroll
            for (int tl = 0; tl < 4; tl++) {
                float q = fmaf(d[tl], qc.x, qc.y);
                float e = ex2a(-q * q);
                force[tl] = fmaf(q * wq, e, force[tl]);
            }
        }

        #pragma unroll
        for (int tl = 0; tl < 4; tl++) {
            int t = tg * 4 + tl;
            const float* ci = coords + (t * NRES + i) * 3;
            float coef = -KCB * force[tl] * frcpa(d[tl]);
            acc[tl][0] = fmaf(coef, s_cbj[t * 3 + 0] - ci[0], acc[tl][0]);
            acc[tl][1] = fmaf(coef, s_cbj[t * 3 + 1] - ci[1], acc[tl][1]);
            acc[tl][2] = fmaf(coef, s_cbj[t * 3 + 2] - ci[2], acc[tl][2]);
        }
    }

    // ---- Reduce over the 32 i-lanes of each warp, then 4 warps per tg ----
    #pragma unroll
    for (int tl = 0; tl < 4; tl++) {
        #pragma unroll
        for (int c = 0; c < 3; c++) {
            float v = acc[tl][c];
            v += __shfl_down_sync(0xffffffffu, v, 16);
            v += __shfl_down_sync(0xffffffffu, v, 8);
            v += __shfl_down_sync(0xffffffffu, v, 4);
            v += __shfl_down_sync(0xffffffffu, v, 2);
            v += __shfl_down_sync(0xffffffffu, v, 1);
            if (lane == 0) s_part[warp][tl * 3 + c] = v;
        }
    }
    __syncthreads();
    if (tid < 24) {
        int tg2 = tid / 12, idx = tid - tg2 * 12;
        float s = s_part[tg2 * 4 + 0][idx] + s_part[tg2 * 4 + 1][idx]
                + s_part[tg2 * 4 + 2][idx] + s_part[tg2 * 4 + 3][idx];
        int tl = idx / 3, c = idx - tl * 3;
        int t = tg2 * 4 + tl;
        atomicAdd(&out[(t * NRES + j) * 3 + c], s);
    }
}

extern "C" void kernel_launch(void* const* d_in, const int* in_sizes, int n_in,
                              void* d_out, int out_size) {
    const float* coords  = (const float*)d_in[0];
    const float* gw      = (const float*)d_in[1];
    const float* centres = (const float*)d_in[2];
    const float* sigmas  = (const float*)d_in[3];
    float* out = (float*)d_out;

    zero_kernel<<<(NT * NRES * 3 + 255) / 256, 256>>>(out, NT * NRES * 3);
    dim3 grid(NCHUNK, NRES);
    force_folder_kernel<<<grid, 256>>>(coords, gw, centres, sigmas, out);
}

// round 13
// speedup vs baseline: 2.4368x; 1.0850x over previous
#include <cuda_runtime.h>

typedef unsigned long long ull;

#define NT     8
#define NRES   500
#define NBINS  34
#define NHALF  17
#define KCB    150.0f
#define WPAD   35      // stride-35 LDS rows: conflict-free
#define ROWS   128
#define NCHUNK 4

__device__ __forceinline__ float ex2a(float x)  { float r; asm("ex2.approx.ftz.f32 %0, %1;"  : "=f"(r) : "f"(x)); return r; }
__device__ __forceinline__ float frcpa(float x) { float r; asm("rcp.approx.ftz.f32 %0, %1;"  : "=f"(r) : "f"(x)); return r; }
__device__ __forceinline__ float fsqrta(float x){ float r; asm("sqrt.approx.ftz.f32 %0, %1;" : "=f"(r) : "f"(x)); return r; }

__device__ __forceinline__ ull pk2(float lo, float hi) {
    ull r; asm("mov.b64 %0, {%1, %2};" : "=l"(r) : "f"(lo), "f"(hi)); return r;
}
__device__ __forceinline__ float2 upk2(ull v) {
    float2 f; asm("mov.b64 {%0, %1}, %2;" : "=f"(f.x), "=f"(f.y) : "l"(v)); return f;
}
__device__ __forceinline__ ull mul2_(ull a, ull b) {
    ull r; asm("mul.rn.f32x2 %0, %1, %2;" : "=l"(r) : "l"(a), "l"(b)); return r;
}
__device__ __forceinline__ ull add2_(ull a, ull b) {
    ull r; asm("add.rn.f32x2 %0, %1, %2;" : "=l"(r) : "l"(a), "l"(b)); return r;
}
__device__ __forceinline__ ull fma2_(ull a, ull b, ull c) {
    ull r; asm("fma.rn.f32x2 %0, %1, %2, %3;" : "=l"(r) : "l"(a), "l"(b), "l"(c)); return r;
}

__global__ void zero_kernel(float* __restrict__ out, int n) {
    int i = blockIdx.x * blockDim.x + threadIdx.x;
    if (i < n) out[i] = 0.0f;
}

// Layout as R12: tg = tid>>7 -> trajectories tg*4..tg*4+3; il = tid&127 -> i row.
// Uniform-grid fast path: Gaussian g_b via multiplicative recurrence, two sweeps
// (bins 0..16 forward, 33..17 backward) so anchors never underflow where it matters.
// F = sum_b z_b * w_b * g_b,  z=(d-c)/sigma;  ref force = -F/sigma^2;
// coef = -K*force/d = (K/sigma^2) * F / d.
__global__ __launch_bounds__(256, 3) void force_folder_kernel(
    const float* __restrict__ coords,   // [NT, NRES, 3]
    const float* __restrict__ gw,       // [NRES, NRES, NBINS]
    const float* __restrict__ centres,  // [NBINS]
    const float* __restrict__ sigmas,   // [NBINS]
    float* __restrict__ out)            // [NT, NRES, 3], pre-zeroed
{
    const int chunk = blockIdx.x;
    const int j     = blockIdx.y;
    const int tid   = threadIdx.x;
    const int warp  = tid >> 5;
    const int lane  = tid & 31;
    const int tg    = tid >> 7;
    const int il    = tid & 127;

    __shared__ float s_w[ROWS * WPAD];
    __shared__ float s_cbj[NT * 3];
    __shared__ float s_part[8][12];

    if (tid < NT * 3) {
        int t = tid / 3, cc = tid - t * 3;
        s_cbj[tid] = coords[(t * NRES + j) * 3 + cc];
    }

    // ---- Cooperative coalesced staging of 128 weight rows (as R12) ----
    {
        const int g = warp & 3, h = warp >> 2;
        const int rbase = g * 32 + h * 16;
        #pragma unroll
        for (int it = 0; it < 9; it++) {
            int k = it * 32 + lane;
            if (k < 16 * 17) {
                int r = k / 17;
                int c = k - r * 17;
                int rl = rbase + r;
                int rg2 = min(chunk * ROWS + rl, NRES - 1);
                const float2 w2 = *(const float2*)(gw + ((long)rg2 * NRES + j) * NBINS + 2 * c);
                s_w[rl * WPAD + 2 * c]     = w2.x;
                s_w[rl * WPAD + 2 * c + 1] = w2.y;
            }
        }
    }

    // ---- Uniform-grid check (also the staging barrier) ----
    const float c0 = __ldg(centres);
    const float dc = __ldg(centres + 1) - c0;
    const float sg = __ldg(sigmas);
    int okp = 1;
    if (tid < NBINS) {
        float cb = __ldg(centres + tid);
        float sb = __ldg(sigmas + tid);
        okp = (fabsf(sb - sg) <= 1e-5f * fabsf(sg)) &&
              (fabsf(cb - fmaf((float)tid, dc, c0)) <= 1e-4f * (fabsf(cb) + 1.0f));
    }
    const int uniform = __syncthreads_and(okp);

    const float invs  = 1.0f / sg;
    const float delta = dc * invs;
    const float Cq    = -0.72134752044f;              // -0.5 * log2(e)
    const float A     = delta * 1.44269504089f;       // delta * log2(e)
    const float B     = Cq * delta * delta;           // -0.5 delta^2 log2(e)
    const float v     = ex2a(2.0f * B);               // exp(-delta^2)

    float acc[4][3];
    #pragma unroll
    for (int tl = 0; tl < 4; tl++) { acc[tl][0] = 0.f; acc[tl][1] = 0.f; acc[tl][2] = 0.f; }

    const int i = chunk * ROWS + il;
    if (i < NRES) {
        const float* __restrict__ wrow = s_w + il * WPAD;

        float d[4], F[4];
        #pragma unroll
        for (int tl = 0; tl < 4; tl++) {
            int t = tg * 4 + tl;
            const float* ci = coords + (t * NRES + i) * 3;
            float dx = s_cbj[t * 3 + 0] - ci[0];
            float dy = s_cbj[t * 3 + 1] - ci[1];
            float dz = s_cbj[t * 3 + 2] - ci[2];
            float ss = fmaf(dx, dx, fmaf(dy, dy, dz * dz));
            d[tl] = fminf(fmaxf(fsqrta(ss), 0.1f), 40.0f);
        }

        float cs;   // final scale: coef = cs * F * (1/d)
        if (uniform) {
            // per-t scalar anchors
            float z0s[4], g0s[4], m0s[4], z3s[4], g3s[4], n3s[4];
            #pragma unroll
            for (int tl = 0; tl < 4; tl++) {
                float z0 = (d[tl] - c0) * invs;
                z0s[tl] = z0;
                g0s[tl] = ex2a(Cq * z0 * z0);
                m0s[tl] = ex2a(fmaf(z0, A, B));
                float z3 = z0 - 33.0f * delta;
                z3s[tl] = z3;
                g3s[tl] = ex2a(Cq * z3 * z3);
                n3s[tl] = ex2a(fmaf(-z3, A, B));
            }

            ull fz[2], fg[2], fm[2], bz[2], bg[2], bm[2], a2[2];
            #pragma unroll
            for (int p = 0; p < 2; p++) {
                fz[p] = pk2(z0s[2*p], z0s[2*p+1]);
                fg[p] = pk2(g0s[2*p], g0s[2*p+1]);
                fm[p] = pk2(m0s[2*p], m0s[2*p+1]);
                bz[p] = pk2(z3s[2*p], z3s[2*p+1]);
                bg[p] = pk2(g3s[2*p], g3s[2*p+1]);
                bm[p] = pk2(n3s[2*p], n3s[2*p+1]);
                a2[p] = pk2(0.0f, 0.0f);
            }
            const ull v2  = pk2(v, v);
            const ull dl2 = pk2(delta, delta);
            const ull nd2 = pk2(-delta, -delta);

            #pragma unroll
            for (int k = 0; k < NHALF; k++) {
                float wf = wrow[k];
                float wb = wrow[33 - k];
                ull wf2 = pk2(wf, wf);
                ull wb2 = pk2(wb, wb);
                #pragma unroll
                for (int p = 0; p < 2; p++) {
                    // forward bin k: use then update
                    a2[p] = fma2_(wf2, mul2_(fz[p], fg[p]), a2[p]);
                    fg[p] = mul2_(fg[p], fm[p]);
                    fm[p] = mul2_(fm[p], v2);
                    fz[p] = add2_(fz[p], nd2);
                    // backward bin 33-k: use then update
                    a2[p] = fma2_(wb2, mul2_(bz[p], bg[p]), a2[p]);
                    bg[p] = mul2_(bg[p], bm[p]);
                    bm[p] = mul2_(bm[p], v2);
                    bz[p] = add2_(bz[p], dl2);
                }
            }
            float2 r0 = upk2(a2[0]), r1 = upk2(a2[1]);
            F[0] = r0.x; F[1] = r0.y; F[2] = r1.x; F[3] = r1.y;
            cs = KCB * invs * invs;
        } else {
            // generic fallback (non-uniform bins): reference-accurate scalar path
            #pragma unroll
            for (int tl = 0; tl < 4; tl++) F[tl] = 0.0f;
            for (int b = 0; b < NBINS; b++) {
                float cb  = __ldg(centres + b);
                float sb  = __ldg(sigmas + b);
                float isb = 1.0f / sb;
                float w   = wrow[b] * isb * isb * isb;
                #pragma unroll
                for (int tl = 0; tl < 4; tl++) {
                    float u = (d[tl] - cb) * isb;
                    float e = ex2a(Cq * u * u);
                    F[tl] = fmaf(-u * w, e, F[tl]);   // ref 'forces' integrand
                }
            }
            cs = -KCB;
        }

        #pragma unroll
        for (int tl = 0; tl < 4; tl++) {
            int t = tg * 4 + tl;
            const float* ci = coords + (t * NRES + i) * 3;
            float coef = cs * F[tl] * frcpa(d[tl]);
            acc[tl][0] = fmaf(coef, s_cbj[t * 3 + 0] - ci[0], acc[tl][0]);
            acc[tl][1] = fmaf(coef, s_cbj[t * 3 + 1] - ci[1], acc[tl][1]);
            acc[tl][2] = fmaf(coef, s_cbj[t * 3 + 2] - ci[2], acc[tl][2]);
        }
    }

    // ---- Reduce 32 i-lanes per warp, then 4 warps per tg, atomic to out ----
    #pragma unroll
    for (int tl = 0; tl < 4; tl++) {
        #pragma unroll
        for (int c = 0; c < 3; c++) {
            float val = acc[tl][c];
            val += __shfl_down_sync(0xffffffffu, val, 16);
            val += __shfl_down_sync(0xffffffffu, val, 8);
            val += __shfl_down_sync(0xffffffffu, val, 4);
            val += __shfl_down_sync(0xffffffffu, val, 2);
            val += __shfl_down_sync(0xffffffffu, val, 1);
            if (lane == 0) s_part[warp][tl * 3 + c] = val;
        }
    }
    __syncthreads();
    if (tid < 24) {
        int tg2 = tid / 12, idx = tid - tg2 * 12;
        float s = s_part[tg2 * 4 + 0][idx] + s_part[tg2 * 4 + 1][idx]
                + s_part[tg2 * 4 + 2][idx] + s_part[tg2 * 4 + 3][idx];
        int tl = idx / 3, c = idx - tl * 3;
        int t = tg2 * 4 + tl;
        atomicAdd(&out[(t * NRES + j) * 3 + c], s);
    }
}

extern "C" void kernel_launch(void* const* d_in, const int* in_sizes, int n_in,
                              void* d_out, int out_size) {
    const float* coords  = (const float*)d_in[0];
    const float* gw      = (const float*)d_in[1];
    const float* centres = (const float*)d_in[2];
    const float* sigmas  = (const float*)d_in[3];
    float* out = (float*)d_out;

    zero_kernel<<<(NT * NRES * 3 + 255) / 256, 256>>>(out, NT * NRES * 3);
    dim3 grid(NCHUNK, NRES);
    force_folder_kernel<<<grid, 256>>>(coords, gw, centres, sigmas, out);
}

// round 14
// speedup vs baseline: 2.6094x; 1.0708x over previous
#include <cuda_runtime.h>

typedef unsigned long long ull;

#define NT     8
#define NRES   500
#define NBINS  34
#define NHALF  17
#define KCB    150.0f
#define WPAD   35      // stride-35 LDS rows: conflict-free
#define ROWS   128
#define NCHUNK 4

__device__ __forceinline__ float ex2a(float x)  { float r; asm("ex2.approx.ftz.f32 %0, %1;"  : "=f"(r) : "f"(x)); return r; }
__device__ __forceinline__ float frcpa(float x) { float r; asm("rcp.approx.ftz.f32 %0, %1;"  : "=f"(r) : "f"(x)); return r; }
__device__ __forceinline__ float fsqrta(float x){ float r; asm("sqrt.approx.ftz.f32 %0, %1;" : "=f"(r) : "f"(x)); return r; }

__device__ __forceinline__ ull pk2(float lo, float hi) {
    ull r; asm("mov.b64 %0, {%1, %2};" : "=l"(r) : "f"(lo), "f"(hi)); return r;
}
__device__ __forceinline__ float2 upk2(ull v) {
    float2 f; asm("mov.b64 {%0, %1}, %2;" : "=f"(f.x), "=f"(f.y) : "l"(v)); return f;
}
__device__ __forceinline__ ull mul2_(ull a, ull b) {
    ull r; asm("mul.rn.f32x2 %0, %1, %2;" : "=l"(r) : "l"(a), "l"(b)); return r;
}
__device__ __forceinline__ ull fma2_(ull a, ull b, ull c) {
    ull r; asm("fma.rn.f32x2 %0, %1, %2, %3;" : "=l"(r) : "l"(a), "l"(b), "l"(c)); return r;
}

__global__ void zero_kernel(float* __restrict__ out, int n) {
    int i = blockIdx.x * blockDim.x + threadIdx.x;
    if (i < n) out[i] = 0.0f;
}

// Uniform-grid fast path via moments:
//   z_b = z0 - b*delta  (global, both sweep directions)
//   F = sum_b w_b z_b g_b = z0*S0 - delta*S1,  S0 = sum w g,  S1 = sum b w g
//   g via multiplicative recurrence, two sweeps (0..16 fwd, 33..17 bwd) so
//   anchors never underflow where terms matter.
// ref force = -F/sigma^2;  coef = -K*force/d = (K/sigma^2)*F/d.
__global__ __launch_bounds__(256, 4) void force_folder_kernel(
    const float* __restrict__ coords,   // [NT, NRES, 3]
    const float* __restrict__ gw,       // [NRES, NRES, NBINS]
    const float* __restrict__ centres,  // [NBINS]
    const float* __restrict__ sigmas,   // [NBINS]
    float* __restrict__ out)            // [NT, NRES, 3], pre-zeroed
{
    const int chunk = blockIdx.x;
    const int j     = blockIdx.y;
    const int tid   = threadIdx.x;
    const int warp  = tid >> 5;
    const int lane  = tid & 31;
    const int tg    = tid >> 7;
    const int il    = tid & 127;

    __shared__ float s_w[ROWS * WPAD];
    __shared__ float s_cbj[NT * 3];
    __shared__ float s_part[8][12];

    if (tid < NT * 3) {
        int t = tid / 3, cc = tid - t * 3;
        s_cbj[tid] = coords[(t * NRES + j) * 3 + cc];
    }

    // ---- Cooperative coalesced staging of 128 weight rows ----
    {
        const int g = warp & 3, h = warp >> 2;
        const int rbase = g * 32 + h * 16;
        #pragma unroll
        for (int it = 0; it < 9; it++) {
            int k = it * 32 + lane;
            if (k < 16 * 17) {
                int r = k / 17;
                int c = k - r * 17;
                int rl = rbase + r;
                int rg2 = min(chunk * ROWS + rl, NRES - 1);
                const float2 w2 = *(const float2*)(gw + ((long)rg2 * NRES + j) * NBINS + 2 * c);
                s_w[rl * WPAD + 2 * c]     = w2.x;
                s_w[rl * WPAD + 2 * c + 1] = w2.y;
            }
        }
    }

    // ---- Uniform-grid check (doubles as the staging barrier) ----
    const float c0 = __ldg(centres);
    const float dc = __ldg(centres + 1) - c0;
    const float sg = __ldg(sigmas);
    int okp = 1;
    if (tid < NBINS) {
        float cb = __ldg(centres + tid);
        float sb = __ldg(sigmas + tid);
        okp = (fabsf(sb - sg) <= 1e-5f * fabsf(sg)) &&
              (fabsf(cb - fmaf((float)tid, dc, c0)) <= 1e-4f * (fabsf(cb) + 1.0f));
    }
    const int uniform = __syncthreads_and(okp);

    const float invs  = 1.0f / sg;
    const float delta = dc * invs;
    const float Cq    = -0.72134752044f;              // -0.5 * log2(e)
    const float A     = delta * 1.44269504089f;       // delta * log2(e)
    const float B     = Cq * delta * delta;           // -0.5 delta^2 log2(e)
    const float v     = ex2a(2.0f * B);               // exp(-delta^2)

    float acc[4][3];
    #pragma unroll
    for (int tl = 0; tl < 4; tl++) { acc[tl][0] = 0.f; acc[tl][1] = 0.f; acc[tl][2] = 0.f; }

    const int i = chunk * ROWS + il;
    if (i < NRES) {
        const float* __restrict__ wrow = s_w + il * WPAD;

        float d[4], F[4];
        #pragma unroll
        for (int tl = 0; tl < 4; tl++) {
            int t = tg * 4 + tl;
            const float* ci = coords + (t * NRES + i) * 3;
            float dx = s_cbj[t * 3 + 0] - ci[0];
            float dy = s_cbj[t * 3 + 1] - ci[1];
            float dz = s_cbj[t * 3 + 2] - ci[2];
            float ss = fmaf(dx, dx, fmaf(dy, dy, dz * dz));
            d[tl] = fminf(fmaxf(fsqrta(ss), 0.1f), 40.0f);
        }

        float cs;   // final: coef = cs * F * (1/d)
        if (uniform) {
            const float mc0 = -c0 * invs;
            ull fg[2], fm[2], bg[2], bm[2], S0[2], S1[2];
            #pragma unroll
            for (int p = 0; p < 2; p++) {
                float z0a = fmaf(d[2*p],   invs, mc0);
                float z0b = fmaf(d[2*p+1], invs, mc0);
                float z3a = z0a - 33.0f * delta;
                float z3b = z0b - 33.0f * delta;
                fg[p] = pk2(ex2a(Cq * z0a * z0a),   ex2a(Cq * z0b * z0b));
                fm[p] = pk2(ex2a(fmaf(z0a, A, B)),  ex2a(fmaf(z0b, A, B)));
                bg[p] = pk2(ex2a(Cq * z3a * z3a),   ex2a(Cq * z3b * z3b));
                bm[p] = pk2(ex2a(fmaf(-z3a, A, B)), ex2a(fmaf(-z3b, A, B)));
                S0[p] = 0ull;
                S1[p] = 0ull;
            }
            const ull v2 = pk2(v, v);

            #pragma unroll
            for (int k = 0; k < NHALF; k++) {
                float wf  = wrow[k];
                float wb  = wrow[33 - k];
                float wfb = wf * (float)k;          // FMUL-imm (k compile-time)
                float wbb = wb * (float)(33 - k);
                ull wf2  = pk2(wf,  wf);
                ull wb2  = pk2(wb,  wb);
                ull wfb2 = pk2(wfb, wfb);
                ull wbb2 = pk2(wbb, wbb);
                #pragma unroll
                for (int p = 0; p < 2; p++) {
                    S0[p] = fma2_(wf2,  fg[p], S0[p]);
                    S1[p] = fma2_(wfb2, fg[p], S1[p]);
                    fg[p] = mul2_(fg[p], fm[p]);
                    fm[p] = mul2_(fm[p], v2);
                    S0[p] = fma2_(wb2,  bg[p], S0[p]);
                    S1[p] = fma2_(wbb2, bg[p], S1[p]);
                    bg[p] = mul2_(bg[p], bm[p]);
                    bm[p] = mul2_(bm[p], v2);
                }
            }

            const ull nd2 = pk2(-delta, -delta);
            #pragma unroll
            for (int p = 0; p < 2; p++) {
                ull z02 = pk2(fmaf(d[2*p],   invs, mc0),
                              fmaf(d[2*p+1], invs, mc0));
                ull F2  = fma2_(S1[p], nd2, mul2_(S0[p], z02));  // z0*S0 - d*S1
                float2 r = upk2(F2);
                F[2*p]   = r.x;
                F[2*p+1] = r.y;
            }
            cs = KCB * invs * invs;
        } else {
            // generic fallback (non-uniform bins): reference-accurate scalar path
            #pragma unroll
            for (int tl = 0; tl < 4; tl++) F[tl] = 0.0f;
            for (int b = 0; b < NBINS; b++) {
                float cb  = __ldg(centres + b);
                float sb  = __ldg(sigmas + b);
                float isb = 1.0f / sb;
                float w   = wrow[b] * isb * isb * isb;
                #pragma unroll
                for (int tl = 0; tl < 4; tl++) {
                    float u = (d[tl] - cb) * isb;
                    float e = ex2a(Cq * u * u);
                    F[tl] = fmaf(-u * w, e, F[tl]);
                }
            }
            cs = -KCB;
        }

        #pragma unroll
        for (int tl = 0; tl < 4; tl++) {
            int t = tg * 4 + tl;
            const float* ci = coords + (t * NRES + i) * 3;
            float coef = cs * F[tl] * frcpa(d[tl]);
            acc[tl][0] = fmaf(coef, s_cbj[t * 3 + 0] - ci[0], acc[tl][0]);
            acc[tl][1] = fmaf(coef, s_cbj[t * 3 + 1] - ci[1], acc[tl][1]);
            acc[tl][2] = fmaf(coef, s_cbj[t * 3 + 2] - ci[2], acc[tl][2]);
        }
    }

    // ---- Reduce 32 i-lanes per warp, then 4 warps per tg, atomic to out ----
    #pragma unroll
    for (int tl = 0; tl < 4; tl++) {
        #pragma unroll
        for (int c = 0; c < 3; c++) {
            float val = acc[tl][c];
            val += __shfl_down_sync(0xffffffffu, val, 16);
            val += __shfl_down_sync(0xffffffffu, val, 8);
            val += __shfl_down_sync(0xffffffffu, val, 4);
            val += __shfl_down_sync(0xffffffffu, val, 2);
            val += __shfl_down_sync(0xffffffffu, val, 1);
            if (lane == 0) s_part[warp][tl * 3 + c] = val;
        }
    }
    __syncthreads();
    if (tid < 24) {
        int tg2 = tid / 12, idx = tid - tg2 * 12;
        float s = s_part[tg2 * 4 + 0][idx] + s_part[tg2 * 4 + 1][idx]
                + s_part[tg2 * 4 + 2][idx] + s_part[tg2 * 4 + 3][idx];
        int tl = idx / 3, c = idx - tl * 3;
        int t = tg2 * 4 + tl;
        atomicAdd(&out[(t * NRES + j) * 3 + c], s);
    }
}

extern "C" void kernel_launch(void* const* d_in, const int* in_sizes, int n_in,
                              void* d_out, int out_size) {
    const float* coords  = (const float*)d_in[0];
    const float* gw      = (const float*)d_in[1];
    const float* centres = (const float*)d_in[2];
    const float* sigmas  = (const float*)d_in[3];
    float* out = (float*)d_out;

    zero_kernel<<<(NT * NRES * 3 + 255) / 256, 256>>>(out, NT * NRES * 3);
    dim3 grid(NCHUNK, NRES);
    force_folder_kernel<<<grid, 256>>>(coords, gw, centres, sigmas, out);
}

// round 15
// speedup vs baseline: 2.6327x; 1.0089x over previous
#include <cuda_runtime.h>

typedef unsigned long long ull;

#define NT     8
#define NRES   500
#define NBINS  34
#define NHALF  17
#define KCB    150.0f
#define WPAD   35      // stride-35 LDS rows: conflict-free
#define ROWS   64
#define NCHUNK 8

__device__ __forceinline__ float ex2a(float x)  { float r; asm("ex2.approx.ftz.f32 %0, %1;"  : "=f"(r) : "f"(x)); return r; }
__device__ __forceinline__ float frcpa(float x) { float r; asm("rcp.approx.ftz.f32 %0, %1;"  : "=f"(r) : "f"(x)); return r; }
__device__ __forceinline__ float fsqrta(float x){ float r; asm("sqrt.approx.ftz.f32 %0, %1;" : "=f"(r) : "f"(x)); return r; }

__device__ __forceinline__ ull pk2(float lo, float hi) {
    ull r; asm("mov.b64 %0, {%1, %2};" : "=l"(r) : "f"(lo), "f"(hi)); return r;
}
__device__ __forceinline__ float2 upk2(ull v) {
    float2 f; asm("mov.b64 {%0, %1}, %2;" : "=f"(f.x), "=f"(f.y) : "l"(v)); return f;
}
__device__ __forceinline__ ull mul2_(ull a, ull b) {
    ull r; asm("mul.rn.f32x2 %0, %1, %2;" : "=l"(r) : "l"(a), "l"(b)); return r;
}
__device__ __forceinline__ ull add2_(ull a, ull b) {
    ull r; asm("add.rn.f32x2 %0, %1, %2;" : "=l"(r) : "l"(a), "l"(b)); return r;
}
__device__ __forceinline__ ull fma2_(ull a, ull b, ull c) {
    ull r; asm("fma.rn.f32x2 %0, %1, %2, %3;" : "=l"(r) : "l"(a), "l"(b), "l"(c)); return r;
}

__global__ void zero_kernel(float* __restrict__ out, int n) {
    int i = blockIdx.x * blockDim.x + threadIdx.x;
    if (i < n) out[i] = 0.0f;
}

// Layout: tg = tid>>6 (4 groups) -> trajectories {2tg, 2tg+1};
//         il = tid&63 -> i-row within this block's 64-row chunk.
// Packed lanes = the thread's 2 trajectories.
// Moments with U-trick (no per-bin index muls):
//   S0 = sum w g;  U += S0 each bin  =>  S1f = 17*S0f - Uf, S1b = 16*S0b + Ub
//   F  = z0*(S0f+S0b) - delta*S1 = (z0-17d)S0f + (z0-16d)S0b + d*Uf - d*Ub
// coef = (K/sigma^2) * F / dist.
__global__ __launch_bounds__(256, 5) void force_folder_kernel(
    const float* __restrict__ coords,   // [NT, NRES, 3]
    const float* __restrict__ gw,       // [NRES, NRES, NBINS]
    const float* __restrict__ centres,  // [NBINS]
    const float* __restrict__ sigmas,   // [NBINS]
    float* __restrict__ out)            // [NT, NRES, 3], pre-zeroed
{
    const int chunk = blockIdx.x;
    const int j     = blockIdx.y;
    const int tid   = threadIdx.x;
    const int warp  = tid >> 5;
    const int lane  = tid & 31;
    const int tg    = tid >> 6;     // 0..3 -> trajs {2tg, 2tg+1}
    const int il    = tid & 63;     // i-row lane

    __shared__ float s_w[ROWS * WPAD];
    __shared__ float s_cbj[NT * 3];
    __shared__ float s_part[8][6];

    if (tid < NT * 3) {
        int t = tid / 3, cc = tid - t * 3;
        s_cbj[tid] = coords[(t * NRES + j) * 3 + cc];
    }

    // ---- Cooperative coalesced staging: warp w stages rows [w*8, w*8+8),
    // 17 float2 each (136 float2), lanes spread across rows. ----
    {
        const int rbase = warp * 8;
        #pragma unroll
        for (int it = 0; it < 5; it++) {
            int k = it * 32 + lane;
            if (k < 8 * 17) {
                int r = k / 17;
                int c = k - r * 17;
                int rl = rbase + r;
                int rg2 = min(chunk * ROWS + rl, NRES - 1);
                const float2 w2 = *(const float2*)(gw + ((long)rg2 * NRES + j) * NBINS + 2 * c);
                s_w[rl * WPAD + 2 * c]     = w2.x;
                s_w[rl * WPAD + 2 * c + 1] = w2.y;
            }
        }
    }

    // ---- Uniform-grid check (doubles as the staging barrier) ----
    const float c0 = __ldg(centres);
    const float dc = __ldg(centres + 1) - c0;
    const float sg = __ldg(sigmas);
    int okp = 1;
    if (tid < NBINS) {
        float cb = __ldg(centres + tid);
        float sb = __ldg(sigmas + tid);
        okp = (fabsf(sb - sg) <= 1e-5f * fabsf(sg)) &&
              (fabsf(cb - fmaf((float)tid, dc, c0)) <= 1e-4f * (fabsf(cb) + 1.0f));
    }
    const int uniform = __syncthreads_and(okp);

    const float invs  = 1.0f / sg;
    const float delta = dc * invs;
    const float Cq    = -0.72134752044f;              // -0.5 * log2(e)
    const float A     = delta * 1.44269504089f;       // delta * log2(e)
    const float B     = Cq * delta * delta;           // -0.5 delta^2 log2(e)
    const float v     = ex2a(2.0f * B);               // exp(-delta^2)

    float acc[2][3];
    #pragma unroll
    for (int tl = 0; tl < 2; tl++) { acc[tl][0] = 0.f; acc[tl][1] = 0.f; acc[tl][2] = 0.f; }

    const int i = chunk * ROWS + il;
    if (i < NRES) {
        const float* __restrict__ wrow = s_w + il * WPAD;

        float d[2], F[2];
        #pragma unroll
        for (int tl = 0; tl < 2; tl++) {
            int t = tg * 2 + tl;
            const float* ci = coords + (t * NRES + i) * 3;
            float dx = s_cbj[t * 3 + 0] - ci[0];
            float dy = s_cbj[t * 3 + 1] - ci[1];
            float dz = s_cbj[t * 3 + 2] - ci[2];
            float ss = fmaf(dx, dx, fmaf(dy, dy, dz * dz));
            d[tl] = fminf(fmaxf(fsqrta(ss), 0.1f), 40.0f);
        }

        float cs;   // final: coef = cs * F * (1/d)
        if (uniform) {
            const float mc0 = -c0 * invs;
            const float z0a = fmaf(d[0], invs, mc0);
            const float z0b = fmaf(d[1], invs, mc0);
            const float z3a = z0a - 33.0f * delta;
            const float z3b = z0b - 33.0f * delta;

            ull fg = pk2(ex2a(Cq * z0a * z0a),   ex2a(Cq * z0b * z0b));
            ull fm = pk2(ex2a(fmaf(z0a, A, B)),  ex2a(fmaf(z0b, A, B)));
            ull bg = pk2(ex2a(Cq * z3a * z3a),   ex2a(Cq * z3b * z3b));
            ull bm = pk2(ex2a(fmaf(-z3a, A, B)), ex2a(fmaf(-z3b, A, B)));
            ull S0f = 0ull, S0b = 0ull, Uf = 0ull, Ub = 0ull;
            const ull v2 = pk2(v, v);

            #pragma unroll
            for (int k = 0; k < NHALF; k++) {
                ull wf2 = pk2(wrow[k],      wrow[k]);
                ull wb2 = pk2(wrow[33 - k], wrow[33 - k]);
                S0f = fma2_(wf2, fg, S0f);
                Uf  = add2_(Uf, S0f);
                fg  = mul2_(fg, fm);
                fm  = mul2_(fm, v2);
                S0b = fma2_(wb2, bg, S0b);
                Ub  = add2_(Ub, S0b);
                bg  = mul2_(bg, bm);
                bm  = mul2_(bm, v2);
            }

            // F = (z0-17d)*S0f + (z0-16d)*S0b + d*Uf - d*Ub
            float2 s0f = upk2(S0f), s0b = upk2(S0b), uf = upk2(Uf), ub = upk2(Ub);
            {
                float e0 = z0a - 17.0f * delta, e1 = z0a - 16.0f * delta;
                F[0] = fmaf(e0, s0f.x, fmaf(e1, s0b.x, delta * (uf.x - ub.x)));
                float f0 = z0b - 17.0f * delta, f1 = z0b - 16.0f * delta;
                F[1] = fmaf(f0, s0f.y, fmaf(f1, s0b.y, delta * (uf.y - ub.y)));
            }
            cs = KCB * invs * invs;
        } else {
            // generic fallback (non-uniform bins): reference-accurate scalar path
            F[0] = 0.0f; F[1] = 0.0f;
            for (int b = 0; b < NBINS; b++) {
                float cb  = __ldg(centres + b);
                float sb  = __ldg(sigmas + b);
                float isb = 1.0f / sb;
                float w   = wrow[b] * isb * isb * isb;
                #pragma unroll
                for (int tl = 0; tl < 2; tl++) {
                    float u = (d[tl] - cb) * isb;
                    float e = ex2a(Cq * u * u);
                    F[tl] = fmaf(-u * w, e, F[tl]);
                }
            }
            cs = -KCB;
        }

        #pragma unroll
        for (int tl = 0; tl < 2; tl++) {
            int t = tg * 2 + tl;
            const float* ci = coords + (t * NRES + i) * 3;
            float coef = cs * F[tl] * frcpa(d[tl]);
            acc[tl][0] = fmaf(coef, s_cbj[t * 3 + 0] - ci[0], acc[tl][0]);
            acc[tl][1] = fmaf(coef, s_cbj[t * 3 + 1] - ci[1], acc[tl][1]);
            acc[tl][2] = fmaf(coef, s_cbj[t * 3 + 2] - ci[2], acc[tl][2]);
        }
    }

    // ---- Reduce 32 i-lanes per warp; 2 warps per tg; atomic to out ----
    #pragma unroll
    for (int tl = 0; tl < 2; tl++) {
        #pragma unroll
        for (int c = 0; c < 3; c++) {
            float val = acc[tl][c];
            val += __shfl_down_sync(0xffffffffu, val, 16);
            val += __shfl_down_sync(0xffffffffu, val, 8);
            val += __shfl_down_sync(0xffffffffu, val, 4);
            val += __shfl_down_sync(0xffffffffu, val, 2);
            val += __shfl_down_sync(0xffffffffu, val, 1);
            if (lane == 0) s_part[warp][tl * 3 + c] = val;
        }
    }
    __syncthreads();
    if (tid < 24) {
        int tg2 = tid / 6, idx = tid - tg2 * 6;           // tg2 0..3, idx 0..5
        float s = s_part[tg2 * 2 + 0][idx] + s_part[tg2 * 2 + 1][idx];
        int tl = idx / 3, c = idx - tl * 3;
        int t = tg2 * 2 + tl;
        atomicAdd(&out[(t * NRES + j) * 3 + c], s);
    }
}

extern "C" void kernel_launch(void* const* d_in, const int* in_sizes, int n_in,
                              void* d_out, int out_size) {
    const float* coords  = (const float*)d_in[0];
    const float* gw      = (const float*)d_in[1];
    const float* centres = (const float*)d_in[2];
    const float* sigmas  = (const float*)d_in[3];
    float* out = (float*)d_out;

    zero_kernel<<<(NT * NRES * 3 + 255) / 256, 256>>>(out, NT * NRES * 3);
    dim3 grid(NCHUNK, NRES);
    force_folder_kernel<<<grid, 256>>>(coords, gw, centres, sigmas, out);
}